// round 2
// baseline (speedup 1.0000x reference)
#include <cuda_runtime.h>
#include <cuda_bf16.h>

// PSAvgPooling: B=8, H=W=64, C=1152 (= 9 bins * 128), N=512 boxes/image,
// 3x3 bins x 3x3 crop samples, bilinear gather, weighted bin-average.
// out[box, c] = (1/81) * sum_{s=0..80} wb[bin(s)] * bilerp(image_b, y_s, x_s, bin(s)*128 + c)

namespace {

constexpr int Hh    = 64;
constexpr int Ww    = 64;
constexpr int Cc    = 1152;   // total channels
constexpr int Csz   = 128;    // channels per bin (Cc / 9)
constexpr int NB    = 3;      // bins per dim
constexpr int NSAMP = 81;     // 9 bins * 9 crop samples

__global__ __launch_bounds__(32) void ps_pool_kernel(
    const float* __restrict__ img,    // [B, H, W, C]
    const float* __restrict__ boxes,  // [B*N, 4]  (y1,x1,y2,x2 normalized)
    const float* __restrict__ wts,    // [9]
    float* __restrict__ out,          // [B*N, 128]
    int nPerImage)
{
    __shared__ int4   s_off[NSAMP];   // element offsets of 4 bilinear corners (incl. bin*128)
    __shared__ float4 s_w[NSAMP];     // bilinear weights * bin weight * inside mask

    const int box_id = blockIdx.x;
    const int b      = box_id / nPerImage;
    const float* __restrict__ image = img + (size_t)b * (Hh * Ww * Cc);
    const float* bx = boxes + (size_t)box_id * 4;
    const int lane = threadIdx.x;

    const float y1 = bx[0], x1 = bx[1], y2 = bx[2], x2 = bx[3];
    const float step_y = (y2 - y1) * (1.0f / 3.0f);
    const float step_x = (x2 - x1) * (1.0f / 3.0f);

    // ---- Precompute 81 samples (offsets + fused weights) ----
    // sample index s = bin_y*27 + bin_x*9 + py*3 + px
    for (int s = lane; s < NSAMP; s += 32) {
        const int by  = s / 27;
        const int bxn = (s / 9) % 3;
        const int py  = (s / 3) % 3;
        const int px  = s % 3;

        // yy = (y1 + (bin + p)*step) * (H-1), p in {0, 0.5, 1}
        const float yy = (y1 + ((float)by + (float)py * 0.5f) * step_y) * (float)(Hh - 1);
        const float xx = (x1 + ((float)bxn + (float)px * 0.5f) * step_x) * (float)(Ww - 1);

        const float y0f = floorf(yy);
        const float x0f = floorf(xx);
        const float wy = yy - y0f;
        const float wx = xx - x0f;
        const int y0 = (int)y0f;
        const int x0 = (int)x0f;

        // reference clips each corner index independently
        const int y0c = min(max(y0,     0), Hh - 1);
        const int y1c = min(max(y0 + 1, 0), Hh - 1);
        const int x0c = min(max(x0,     0), Ww - 1);
        const int x1c = min(max(x0 + 1, 0), Ww - 1);

        const bool inside = (yy >= 0.0f) && (yy <= (float)(Hh - 1)) &&
                            (xx >= 0.0f) && (xx <= (float)(Ww - 1));
        const int bin = by * NB + bxn;
        const float wb = inside ? wts[bin] : 0.0f;
        const int cb = bin * Csz;

        s_off[s] = make_int4((y0c * Ww + x0c) * Cc + cb,
                             (y0c * Ww + x1c) * Cc + cb,
                             (y1c * Ww + x0c) * Cc + cb,
                             (y1c * Ww + x1c) * Cc + cb);
        s_w[s] = make_float4(wb * (1.0f - wy) * (1.0f - wx),
                             wb * (1.0f - wy) * wx,
                             wb * wy * (1.0f - wx),
                             wb * wy * wx);
    }
    __syncwarp();

    // ---- Main loop: each lane owns 4 channels (float4), iterates all 81 samples ----
    const float* __restrict__ base = image + lane * 4;
    float4 acc = make_float4(0.f, 0.f, 0.f, 0.f);

    #pragma unroll 3
    for (int s = 0; s < NSAMP; s++) {
        const int4   off = s_off[s];
        const float4 w   = s_w[s];
        const float4 v0 = __ldg((const float4*)(base + off.x));
        const float4 v1 = __ldg((const float4*)(base + off.y));
        const float4 v2 = __ldg((const float4*)(base + off.z));
        const float4 v3 = __ldg((const float4*)(base + off.w));
        acc.x += w.x * v0.x + w.y * v1.x + w.z * v2.x + w.w * v3.x;
        acc.y += w.x * v0.y + w.y * v1.y + w.z * v2.y + w.w * v3.y;
        acc.z += w.x * v0.z + w.y * v1.z + w.z * v2.z + w.w * v3.z;
        acc.w += w.x * v0.w + w.y * v1.w + w.z * v2.w + w.w * v3.w;
    }

    const float inv = 1.0f / 81.0f;  // mean over 9 samples, then /9 bins
    float4 o;
    o.x = acc.x * inv;
    o.y = acc.y * inv;
    o.z = acc.z * inv;
    o.w = acc.w * inv;
    reinterpret_cast<float4*>(out)[(size_t)box_id * (Csz / 4) + lane] = o;
}

} // namespace

extern "C" void kernel_launch(void* const* d_in, const int* in_sizes, int n_in,
                              void* d_out, int out_size) {
    const float* img   = (const float*)d_in[0];  // [B,64,64,1152] fp32
    const float* boxes = (const float*)d_in[1];  // [B,N,4] fp32
    const float* wts   = (const float*)d_in[2];  // [9] fp32
    float* out = (float*)d_out;                  // [B*N, 128] fp32

    const int B          = in_sizes[0] / (Hh * Ww * Cc);
    const int totalBoxes = in_sizes[1] / 4;
    const int nPerImage  = totalBoxes / B;

    ps_pool_kernel<<<totalBoxes, 32>>>(img, boxes, wts, out, nPerImage);
}

// round 5
// speedup vs baseline: 1.0587x; 1.0587x over previous
#include <cuda_runtime.h>
#include <cuda_bf16.h>

// PSAvgPooling: B=8, H=W=64, C=1152 (= 9 bins * 128), N=512 boxes/image,
// 3x3 bins x 3x3 crop samples, bilinear gather, weighted bin-average.
// out[box, c] = (1/81) * sum_{s=0..80} wb[bin(s)] * bilerp(image_b, y_s, x_s, bin(s)*128 + c)
//
// R4 = R2 resubmit, third attempt (R3/R4 bench errors were container-infra flakes;
// same error class hit the empty stub in R0). Design under test:
//   4 warps per box (samples split across warps) + smem reduction.
//   Byte offsets precomputed (no per-load IMAD-shift). Unroll 4.

namespace {

constexpr int Hh    = 64;
constexpr int Ww    = 64;
constexpr int Cc    = 1152;   // total channels
constexpr int Csz   = 128;    // channels per bin (Cc / 9)
constexpr int NB    = 3;      // bins per dim
constexpr int NSAMP = 81;     // 9 bins * 9 crop samples
constexpr int NWARP = 4;      // warps per box

__global__ __launch_bounds__(NWARP * 32, 8) void ps_pool_kernel(
    const float* __restrict__ img,    // [B, H, W, C]
    const float* __restrict__ boxes,  // [B*N, 4]  (y1,x1,y2,x2 normalized)
    const float* __restrict__ wts,    // [9]
    float* __restrict__ out,          // [B*N, 128]
    int nPerImage)
{
    __shared__ int4   s_off[NSAMP];        // BYTE offsets of 4 bilinear corners (incl. bin*128)
    __shared__ float4 s_w[NSAMP];          // bilinear weights * bin weight * inside mask
    __shared__ float4 s_red[NWARP][32];    // per-warp partial accumulators

    const int box_id = blockIdx.x;
    const int b      = box_id / nPerImage;
    const float* __restrict__ image = img + (size_t)b * (Hh * Ww * Cc);
    const float* bx = boxes + (size_t)box_id * 4;
    const int tid  = threadIdx.x;
    const int lane = tid & 31;
    const int warp = tid >> 5;

    const float y1 = bx[0], x1 = bx[1], y2 = bx[2], x2 = bx[3];
    const float step_y = (y2 - y1) * (1.0f / 3.0f);
    const float step_x = (x2 - x1) * (1.0f / 3.0f);

    // ---- Precompute 81 samples (byte offsets + fused weights), one thread each ----
    if (tid < NSAMP) {
        const int s   = tid;
        const int by  = s / 27;
        const int bxn = (s / 9) % 3;
        const int py  = (s / 3) % 3;
        const int px  = s % 3;

        // yy = (y1 + (bin + p)*step) * (H-1), p in {0, 0.5, 1}
        const float yy = (y1 + ((float)by + (float)py * 0.5f) * step_y) * (float)(Hh - 1);
        const float xx = (x1 + ((float)bxn + (float)px * 0.5f) * step_x) * (float)(Ww - 1);

        const float y0f = floorf(yy);
        const float x0f = floorf(xx);
        const float wy = yy - y0f;
        const float wx = xx - x0f;
        const int y0 = (int)y0f;
        const int x0 = (int)x0f;

        // reference clips each corner index independently
        const int y0c = min(max(y0,     0), Hh - 1);
        const int y1c = min(max(y0 + 1, 0), Hh - 1);
        const int x0c = min(max(x0,     0), Ww - 1);
        const int x1c = min(max(x0 + 1, 0), Ww - 1);

        const bool inside = (yy >= 0.0f) && (yy <= (float)(Hh - 1)) &&
                            (xx >= 0.0f) && (xx <= (float)(Ww - 1));
        const int bin = by * NB + bxn;
        const float wb = inside ? wts[bin] : 0.0f;
        const int cb = bin * Csz;

        // byte offsets (float = 4 bytes)
        s_off[s] = make_int4(((y0c * Ww + x0c) * Cc + cb) * 4,
                             ((y0c * Ww + x1c) * Cc + cb) * 4,
                             ((y1c * Ww + x0c) * Cc + cb) * 4,
                             ((y1c * Ww + x1c) * Cc + cb) * 4);
        s_w[s] = make_float4(wb * (1.0f - wy) * (1.0f - wx),
                             wb * (1.0f - wy) * wx,
                             wb * wy * (1.0f - wx),
                             wb * wy * wx);
    }
    __syncthreads();

    // ---- Each warp walks its slice of the 81 samples; lane owns 4 channels ----
    const char* __restrict__ base = (const char*)image + lane * 16;
    const int s_begin = (warp * NSAMP) / NWARP;
    const int s_end   = ((warp + 1) * NSAMP) / NWARP;

    float4 acc = make_float4(0.f, 0.f, 0.f, 0.f);

    #pragma unroll 4
    for (int s = s_begin; s < s_end; s++) {
        const int4   off = s_off[s];
        const float4 w   = s_w[s];
        const float4 v0 = __ldg((const float4*)(base + off.x));
        const float4 v1 = __ldg((const float4*)(base + off.y));
        const float4 v2 = __ldg((const float4*)(base + off.z));
        const float4 v3 = __ldg((const float4*)(base + off.w));
        acc.x += w.x * v0.x + w.y * v1.x + w.z * v2.x + w.w * v3.x;
        acc.y += w.x * v0.y + w.y * v1.y + w.z * v2.y + w.w * v3.y;
        acc.z += w.x * v0.z + w.y * v1.z + w.z * v2.z + w.w * v3.z;
        acc.w += w.x * v0.w + w.y * v1.w + w.z * v2.w + w.w * v3.w;
    }

    s_red[warp][lane] = acc;
    __syncthreads();

    // ---- First warp reduces the 4 partials and writes out ----
    if (warp == 0) {
        float4 a0 = s_red[0][lane];
        float4 a1 = s_red[1][lane];
        float4 a2 = s_red[2][lane];
        float4 a3 = s_red[3][lane];
        const float inv = 1.0f / 81.0f;  // mean over 9 samples, then /9 bins
        float4 o;
        o.x = (a0.x + a1.x + a2.x + a3.x) * inv;
        o.y = (a0.y + a1.y + a2.y + a3.y) * inv;
        o.z = (a0.z + a1.z + a2.z + a3.z) * inv;
        o.w = (a0.w + a1.w + a2.w + a3.w) * inv;
        reinterpret_cast<float4*>(out)[(size_t)box_id * (Csz / 4) + lane] = o;
    }
}

} // namespace

extern "C" void kernel_launch(void* const* d_in, const int* in_sizes, int n_in,
                              void* d_out, int out_size) {
    const float* img   = (const float*)d_in[0];  // [B,64,64,1152] fp32
    const float* boxes = (const float*)d_in[1];  // [B,N,4] fp32
    const float* wts   = (const float*)d_in[2];  // [9] fp32
    float* out = (float*)d_out;                  // [B*N, 128] fp32

    const int B          = in_sizes[0] / (Hh * Ww * Cc);
    const int totalBoxes = in_sizes[1] / 4;
    const int nPerImage  = totalBoxes / B;

    ps_pool_kernel<<<totalBoxes, NWARP * 32>>>(img, boxes, wts, out, nPerImage);
}